// round 3
// baseline (speedup 1.0000x reference)
#include <cuda_runtime.h>

// Izhikevich 6-neuron network, T sequential steps.
// wid4 (SMSP0, high priority): critical LLBN->EBN->IFN recurrence.
// wid0 (SMSP0, low priority): store warp — fills wid4's stall cycles (diff pipes).
// wid1 (SMSP1): TN->MN feed-forward chain.
// Output: [spikes[5][T] | volts[5][T]]

#define BATCH 32
#define RS_MASK 255       // 256-step rings
#define RING_BATCHES 8

__device__ __forceinline__ void st_rel(int* p, int v) {
    asm volatile("st.release.cta.u32 [%0], %1;" :: "l"(p), "r"(v) : "memory");
}
__device__ __forceinline__ int ld_acq(int* p) {
    int v;
    asm volatile("ld.acquire.cta.u32 %0, [%1];" : "=r"(v) : "l"(p) : "memory");
    return v;
}

__global__ void __launch_bounds__(192, 1)
izh_net4(const float* __restrict__ in_mat, int n_mat,
         const float* __restrict__ w12, float* __restrict__ out, int T) {
    __shared__ __align__(16) float ring0[256 * 8];  // z2,z3,z4,v2,v3,v4,_,_
    __shared__ __align__(16) float ring1[256 * 4];  // z5,v5,z6,v6
    __shared__ float red[6];
    __shared__ int fl[3];  // fl[0]=crit batches, fl[1]=warp1, fl[2]=store consumer

    const int tid = threadIdx.x;
    const int wid = tid >> 5;
    if (tid == 0) { fl[0] = 0; fl[1] = 0; fl[2] = 0; }

    // ---- reduction: sum(input_mat) over all 192 threads ----
    float s = 0.0f;
    for (int i = tid; i < n_mat; i += 192) s += in_mat[i];
    #pragma unroll
    for (int o = 16; o; o >>= 1) s += __shfl_xor_sync(0xffffffffu, s, o);
    if ((tid & 31) == 0) red[wid] = s;
    __syncthreads();

    const int nbat = (T + BATCH - 1) / BATCH;

    // ============ wid4 lane0: CRITICAL chain (SMSP0, outranks wid0) ============
    if (tid == 128) {
        const float total = red[0] + red[1] + red[2] + red[3] + red[4] + red[5];
        const float w0 = w12[0], w1 = w12[1], w2 = w12[2], w3 = w12[3],
                    w4 = w12[4], w5 = w12[5], w6 = w12[6], w7 = w12[7];
        const float z_plus = total * w0;
        const float C2 = 35.0f + 0.25f * w2 * (z_plus * w1);
        const float B2 = 0.25f * w3;        // * z2(t-1)
        const float A2 = -0.25f * w2 * w7;  // * z4(t-1)  (temp feedback)
        const float C3 = 35.0f + 0.25f * (z_plus * w4);
        const float A3 = 0.25f * w5;        // * z2(t)
        const float A4 = 0.25f * w6;        // * z3(t)

        float v2 = -60.0f, u2 = 4.5f;
        float v3 = -64.0f, u3 = -16.0f;
        float v4 = -64.0f, u4 = -16.0f;
        float z2 = 0.0f;      // prev LLBN spike (float)
        bool  s4 = false;     // prev IFN spike (selector)

        int si = 0;
        for (int b = 0; b < nbat; ++b) {
            while (b - ld_acq(&fl[2]) >= RING_BATCHES) { }
            const int n = min(BATCH, T - b * BATCH);
            #pragma unroll 4
            for (int i = 0; i < n; ++i, ++si) {
                // ---- LLBN (a=0.1,b=-0.075,c=-55,d=6) ----
                float h2    = fmaf(v2, 0.01f, 2.25f);
                float k2    = fmaf(u2, -0.25f, C2);
                float core2 = fmaf(v2, h2, k2);
                float base2 = fmaf(z2, B2, core2);     // z2p early
                float q1    = base2 + A2;              // candidate: z4p=1
                bool  c0 = base2 >= 30.0f, c1 = q1 >= 30.0f;
                bool  s2n   = s4 ? c1 : c0;            // resolve on late z4p
                float v12   = s4 ? q1 : base2;
                float nu2   = fmaf(u2, 0.975f, v2 * -0.001875f);
                z2 = s2n ? 1.0f : 0.0f;
                v2 = s2n ? -55.0f : v12;
                u2 = fmaf(z2, 6.0f, nu2);
                // ---- EBN (a=0.02,b=0.25,c=-55,d=0.05) ----
                float h3    = fmaf(v3, 0.01f, 2.25f);
                float k3    = fmaf(u3, -0.25f, C3);
                float core3 = fmaf(v3, h3, k3);
                float r1    = core3 + A3;              // candidate: z2=1
                bool  d0 = core3 >= 30.0f, d1 = r1 >= 30.0f;
                bool  s3n   = s2n ? d1 : d0;
                float v13   = s2n ? r1 : core3;
                float nu3   = fmaf(u3, 0.995f, v3 * 0.00125f);
                float z3    = s3n ? 1.0f : 0.0f;
                v3 = s3n ? -55.0f : v13;
                u3 = fmaf(z3, 0.05f, nu3);
                // ---- IFN (a=0.02,b=0.25,c=-65,d=6) ----
                float h4    = fmaf(v4, 0.01f, 2.25f);
                float k4    = fmaf(u4, -0.25f, 35.0f);
                float core4 = fmaf(v4, h4, k4);
                float t1    = core4 + A4;              // candidate: z3=1
                bool  e0 = core4 >= 30.0f, e1 = t1 >= 30.0f;
                bool  s4n   = s3n ? e1 : e0;
                float v14   = s3n ? t1 : core4;
                float nu4   = fmaf(u4, 0.995f, v4 * 0.00125f);
                float z4    = s4n ? 1.0f : 0.0f;
                v4 = s4n ? -65.0f : v14;
                u4 = fmaf(z4, 6.0f, nu4);
                s4 = s4n;
                // ---- publish ----
                const int idx = (si & RS_MASK) * 8;
                *reinterpret_cast<float4*>(&ring0[idx]) = make_float4(z2, z3, z4, v2);
                *reinterpret_cast<float2*>(&ring0[idx + 4]) = make_float2(v3, v4);
            }
            st_rel(&fl[0], b + 1);
        }
        return;
    }

    // ============ wid1 lane0: TN -> MN (SMSP1) ============
    if (tid == 32) {
        const float w8 = w12[8], w9 = w12[9], w10 = w12[10], w11 = w12[11];
        const float A5 = 0.25f * w9 * w8;  // * z3(t)
        const float B5 = 0.25f * w10;      // * z5(t-1)
        const float A6 = 0.25f * w11;      // * z5(t)
        float v5 = -70.0f, u5 = -14.0f;
        float v6 = -64.0f, u6 = -16.0f;
        float z5 = 0.0f;

        int si = 0;
        for (int b = 0; b < nbat; ++b) {
            while (ld_acq(&fl[0]) <= b) { }
            const int n = min(BATCH, T - b * BATCH);
            #pragma unroll 4
            for (int i = 0; i < n; ++i, ++si) {
                float z3 = ring0[(si & RS_MASK) * 8 + 1];
                // TN (a=0.02,b=0.2,c=-65,d=6)
                float h5    = fmaf(v5, 0.01f, 2.25f);
                float k5    = fmaf(u5, -0.25f, 35.0f);
                float core5 = fmaf(v5, h5, k5);
                float v15   = fmaf(z5, B5, fmaf(z3, A5, core5));
                bool  s5    = v15 >= 30.0f;
                float nu5   = fmaf(u5, 0.995f, v5 * 0.001f);
                z5 = s5 ? 1.0f : 0.0f;
                v5 = s5 ? -65.0f : v15;
                u5 = fmaf(z5, 6.0f, nu5);
                // MN (a=0.02,b=0.25,c=-65,d=6)
                float h6    = fmaf(v6, 0.01f, 2.25f);
                float k6    = fmaf(u6, -0.25f, 35.0f);
                float core6 = fmaf(v6, h6, k6);
                float v16   = fmaf(z5, A6, core6);
                bool  s6    = v16 >= 30.0f;
                float nu6   = fmaf(u6, 0.995f, v6 * 0.00125f);
                float z6    = s6 ? 1.0f : 0.0f;
                v6 = s6 ? -65.0f : v16;
                u6 = fmaf(z6, 6.0f, nu6);

                *reinterpret_cast<float4*>(&ring1[(si & RS_MASK) * 4]) =
                    make_float4(z5, v5, z6, v6);
            }
            st_rel(&fl[1], b + 1);
        }
        return;
    }

    // ============ wid0: store warp (SMSP0, low priority — fills wid4 stalls) ====
    if (wid == 0) {
        const int lane = tid;
        // rows: z2 z3 z4 z5 z6 v2 v3 v4 v5 v6
        // buf:   0  0  0  1  1  0  0  0  1  1   (mask 0x318)
        // col:   0  1  2  0  2  3  4  5  1  3
        for (int b = 0; b < nbat; ++b) {
            while (ld_acq(&fl[1]) <= b) { }
            const int base = b * BATCH;
            const int n = min(BATCH, T - base);
            if ((T & 3) == 0) {
                const int quads = n >> 2;
                const int units = 10 * quads;
                for (int u = lane; u < units; u += 32) {
                    const int row = u / quads;
                    const int q   = u - row * quads;
                    const int st  = base + q * 4;
                    const int buf = (0x318 >> row) & 1;
                    const int col = (row < 8) ? ((0x54320210u >> (4 * row)) & 15)
                                              : ((0x31u >> (4 * (row - 8))) & 15);
                    float x0, x1, x2, x3;
                    if (buf == 0) {
                        x0 = ring0[((st + 0) & RS_MASK) * 8 + col];
                        x1 = ring0[((st + 1) & RS_MASK) * 8 + col];
                        x2 = ring0[((st + 2) & RS_MASK) * 8 + col];
                        x3 = ring0[((st + 3) & RS_MASK) * 8 + col];
                    } else {
                        x0 = ring1[((st + 0) & RS_MASK) * 4 + col];
                        x1 = ring1[((st + 1) & RS_MASK) * 4 + col];
                        x2 = ring1[((st + 2) & RS_MASK) * 4 + col];
                        x3 = ring1[((st + 3) & RS_MASK) * 4 + col];
                    }
                    *reinterpret_cast<float4*>(&out[row * T + st]) =
                        make_float4(x0, x1, x2, x3);
                }
            } else {
                const int units = 10 * n;
                for (int u = lane; u < units; u += 32) {
                    const int row = u / n;
                    const int i   = u - row * n;
                    const int st  = base + i;
                    const int buf = (0x318 >> row) & 1;
                    const int col = (row < 8) ? ((0x54320210u >> (4 * row)) & 15)
                                              : ((0x31u >> (4 * (row - 8))) & 15);
                    float x = buf ? ring1[(st & RS_MASK) * 4 + col]
                                  : ring0[(st & RS_MASK) * 8 + col];
                    out[row * T + st] = x;
                }
            }
            __syncwarp();
            if (lane == 0) st_rel(&fl[2], b + 1);
        }
        return;
    }
    // wid2, wid3, wid5 and non-lane0 threads exit after the reduction.
}

extern "C" void kernel_launch(void* const* d_in, const int* in_sizes, int n_in,
                              void* d_out, int out_size) {
    const float* in_mat = (const float*)d_in[0];
    const float* w12    = (const float*)d_in[1];
    int n_mat = in_sizes[0];
    int T = out_size / 10;
    izh_net4<<<1, 192>>>(in_mat, n_mat, w12, (float*)d_out, T);
}

// round 4
// speedup vs baseline: 1.2465x; 1.2465x over previous
#include <cuda_runtime.h>

// Izhikevich 6-neuron network, T sequential steps.
// warp0 (tid 0,   SMSP0): critical LLBN->EBN->IFN recurrence, f32x2-packed aux math.
// warp1 (tid 32,  SMSP1): TN->MN feed-forward chain, f32x2-packed.
// warp2 (tid 64.., SMSP2..): 32-lane store warp.
// Output: [spikes[5][T] | volts[5][T]]

#define BATCH 32
#define RS_MASK 255
#define RING_BATCHES 8

typedef unsigned long long ull;

__device__ __forceinline__ float fset_ge30(float a) {
    float r;
    asm("set.ge.f32.f32 %0, %1, %2;" : "=f"(r) : "f"(a), "f"(30.0f));
    return r;
}
__device__ __forceinline__ void st_rel(int* p, int v) {
    asm volatile("st.release.cta.u32 [%0], %1;" :: "l"(p), "r"(v) : "memory");
}
__device__ __forceinline__ int ld_acq(int* p) {
    int v;
    asm volatile("ld.acquire.cta.u32 %0, [%1];" : "=r"(v) : "l"(p) : "memory");
    return v;
}
__device__ __forceinline__ ull pk(float lo, float hi) {
    ull r; asm("mov.b64 %0, {%1, %2};" : "=l"(r) : "f"(lo), "f"(hi)); return r;
}
__device__ __forceinline__ void upk(float& lo, float& hi, ull p) {
    asm("mov.b64 {%0, %1}, %2;" : "=f"(lo), "=f"(hi) : "l"(p));
}
__device__ __forceinline__ ull fma2(ull a, ull b, ull c) {
    ull r; asm("fma.rn.f32x2 %0, %1, %2, %3;" : "=l"(r) : "l"(a), "l"(b), "l"(c)); return r;
}
__device__ __forceinline__ ull mul2(ull a, ull b) {
    ull r; asm("mul.rn.f32x2 %0, %1, %2;" : "=l"(r) : "l"(a), "l"(b)); return r;
}

__global__ void __launch_bounds__(128, 1)
izh_net5(const float* __restrict__ in_mat, int n_mat,
         const float* __restrict__ w12, float* __restrict__ out, int T) {
    __shared__ __align__(16) float ring0[256 * 8];  // z2,z3,z4,v4,v2,v3,_,_
    __shared__ __align__(16) float ring1[256 * 4];  // z5,z6,v5,v6
    __shared__ float red[4];
    __shared__ int fl[3];

    const int tid = threadIdx.x;
    if (tid == 0) { fl[0] = 0; fl[1] = 0; fl[2] = 0; }

    // ---- reduction: sum(input_mat) ----
    float s = 0.0f;
    for (int i = tid; i < n_mat; i += 128) s += in_mat[i];
    #pragma unroll
    for (int o = 16; o; o >>= 1) s += __shfl_xor_sync(0xffffffffu, s, o);
    if ((tid & 31) == 0) red[tid >> 5] = s;
    __syncthreads();

    const int nbat = (T + BATCH - 1) / BATCH;

    // ============ warp0 lane0: CRITICAL LLBN -> EBN -> IFN ============
    if (tid == 0) {
        const float total = red[0] + red[1] + red[2] + red[3];
        const float w0 = w12[0], w1 = w12[1], w2 = w12[2], w3 = w12[3],
                    w4 = w12[4], w5 = w12[5], w6 = w12[6], w7 = w12[7];
        const float z_plus = total * w0;
        const float C2 = 35.0f + 0.25f * w2 * (z_plus * w1);
        const float B2 = 0.25f * w3;        // * z2(t-1)
        const float A2 = -0.25f * w2 * w7;  // * z4(t-1)
        const float C3 = 35.0f + 0.25f * (z_plus * w4);
        const float A3 = 0.25f * w5;        // * z2(t)
        const float A4 = 0.25f * w6;        // * z3(t)

        // packed constants for (LLBN, EBN)
        const ull K01  = pk(0.01f, 0.01f);
        const ull K225 = pk(2.25f, 2.25f);
        const ull Kq   = pk(-0.25f, -0.25f);
        const ull C23  = pk(C2, C3);
        const ull al23 = pk(0.975f, 0.995f);
        const ull be23 = pk(-0.001875f, 0.00125f);
        const ull d23  = pk(6.0f, 0.05f);
        const ull c23  = pk(-55.0f, -55.0f);
        const ull m1   = pk(-1.0f, -1.0f);

        ull v23 = pk(-60.0f, -64.0f);
        ull u23 = pk(4.5f, -16.0f);
        float v4 = -64.0f, u4 = -16.0f;
        float z2p = 0.0f, z4p = 0.0f;

        int si = 0;
        for (int b = 0; b < nbat; ++b) {
            while (b - ld_acq(&fl[2]) >= RING_BATCHES) { }
            const int n = min(BATCH, T - b * BATCH);
            #pragma unroll 4
            for (int i = 0; i < n; ++i, ++si) {
                // packed aux (off-chain)
                ull h23 = fma2(v23, K01, K225);
                ull k23 = fma2(u23, Kq, C23);
                ull core23 = fma2(v23, h23, k23);
                float core2, core3; upk(core2, core3, core23);
                // IFN scalar aux
                float h4 = fmaf(v4, 0.01f, 2.25f);
                float k4 = fmaf(u4, -0.25f, 35.0f);
                float core4 = fmaf(v4, h4, k4);
                // scalar spike chain
                float v12 = fmaf(z4p, A2, fmaf(z2p, B2, core2));
                float z2 = fset_ge30(v12);
                float v13 = fmaf(z2, A3, core3);
                float z3 = fset_ge30(v13);
                float v14 = fmaf(z3, A4, core4);
                float z4 = fset_ge30(v14);
                // u updates (old v)
                ull vb23 = mul2(v23, be23);
                ull z23 = pk(z2, z3);
                u23 = fma2(z23, d23, fma2(u23, al23, vb23));
                u4 = fmaf(z4, 6.0f, fmaf(u4, 0.995f, v4 * 0.00125f));
                // v updates
                ull v1_23 = pk(v12, v13);
                ull dd23 = fma2(v1_23, m1, c23);        // c - v1
                v23 = fma2(z23, dd23, v1_23);
                v4 = fmaf(z4, -65.0f - v14, v14);
                z2p = z2; z4p = z4;
                // publish
                const int idx = (si & RS_MASK) * 8;
                *reinterpret_cast<float4*>(&ring0[idx]) = make_float4(z2, z3, z4, v4);
                *reinterpret_cast<ull*>(&ring0[idx + 4]) = v23;  // v2,v3
            }
            st_rel(&fl[0], b + 1);
        }
        return;
    }

    // ============ warp1 lane0: TN -> MN ============
    if (tid == 32) {
        const float w8 = w12[8], w9 = w12[9], w10 = w12[10], w11 = w12[11];
        const float A5 = 0.25f * w9 * w8;  // * z3(t)
        const float B5 = 0.25f * w10;      // * z5(t-1)
        const float A6 = 0.25f * w11;      // * z5(t)

        const ull K01  = pk(0.01f, 0.01f);
        const ull K225 = pk(2.25f, 2.25f);
        const ull Kq   = pk(-0.25f, -0.25f);
        const ull C56  = pk(35.0f, 35.0f);
        const ull al56 = pk(0.995f, 0.995f);
        const ull be56 = pk(0.001f, 0.00125f);
        const ull d56  = pk(6.0f, 6.0f);
        const ull c56  = pk(-65.0f, -65.0f);
        const ull m1   = pk(-1.0f, -1.0f);

        ull v56 = pk(-70.0f, -64.0f);
        ull u56 = pk(-14.0f, -16.0f);
        float z5p = 0.0f;

        int si = 0;
        for (int b = 0; b < nbat; ++b) {
            while (ld_acq(&fl[0]) <= b) { }
            const int n = min(BATCH, T - b * BATCH);
            #pragma unroll 4
            for (int i = 0; i < n; ++i, ++si) {
                float z3 = ring0[(si & RS_MASK) * 8 + 1];
                ull h56 = fma2(v56, K01, K225);
                ull k56 = fma2(u56, Kq, C56);
                ull core56 = fma2(v56, h56, k56);
                float core5, core6; upk(core5, core6, core56);
                float v15 = fmaf(z5p, B5, fmaf(z3, A5, core5));
                float z5 = fset_ge30(v15);
                float v16 = fmaf(z5, A6, core6);
                float z6 = fset_ge30(v16);
                ull vb56 = mul2(v56, be56);
                ull z56 = pk(z5, z6);
                u56 = fma2(z56, d56, fma2(u56, al56, vb56));
                ull v1_56 = pk(v15, v16);
                ull dd56 = fma2(v1_56, m1, c56);
                v56 = fma2(z56, dd56, v1_56);
                z5p = z5;
                const int idx = (si & RS_MASK) * 4;
                *reinterpret_cast<ull*>(&ring1[idx]) = z56;      // z5,z6
                *reinterpret_cast<ull*>(&ring1[idx + 2]) = v56;  // v5,v6
            }
            st_rel(&fl[1], b + 1);
        }
        return;
    }

    // ============ warp2: store warp ============
    if (tid >= 64 && tid < 96) {
        const int lane = tid - 64;
        // rows: z2 z3 z4 z5 z6 v2 v3 v4 v5 v6
        // buf:   0  0  0  1  1  0  0  0  1  1  (0x318)
        // col:   0  1  2  0  1  4  5  3  2  3
        for (int b = 0; b < nbat; ++b) {
            while (ld_acq(&fl[1]) <= b) { }
            const int base = b * BATCH;
            const int n = min(BATCH, T - base);
            if ((T & 3) == 0) {
                const int quads = n >> 2;
                const int units = 10 * quads;
                for (int u = lane; u < units; u += 32) {
                    const int row = u / quads;
                    const int q   = u - row * quads;
                    const int st  = base + q * 4;
                    const int buf = (0x318 >> row) & 1;
                    const int col = (row < 8) ? ((0x35410210u >> (4 * row)) & 15)
                                              : ((0x32u >> (4 * (row - 8))) & 15);
                    float x0, x1, x2, x3;
                    if (buf == 0) {
                        x0 = ring0[((st + 0) & RS_MASK) * 8 + col];
                        x1 = ring0[((st + 1) & RS_MASK) * 8 + col];
                        x2 = ring0[((st + 2) & RS_MASK) * 8 + col];
                        x3 = ring0[((st + 3) & RS_MASK) * 8 + col];
                    } else {
                        x0 = ring1[((st + 0) & RS_MASK) * 4 + col];
                        x1 = ring1[((st + 1) & RS_MASK) * 4 + col];
                        x2 = ring1[((st + 2) & RS_MASK) * 4 + col];
                        x3 = ring1[((st + 3) & RS_MASK) * 4 + col];
                    }
                    *reinterpret_cast<float4*>(&out[row * T + st]) =
                        make_float4(x0, x1, x2, x3);
                }
            } else {
                const int units = 10 * n;
                for (int u = lane; u < units; u += 32) {
                    const int row = u / n;
                    const int i   = u - row * n;
                    const int st  = base + i;
                    const int buf = (0x318 >> row) & 1;
                    const int col = (row < 8) ? ((0x35410210u >> (4 * row)) & 15)
                                              : ((0x32u >> (4 * (row - 8))) & 15);
                    float x = buf ? ring1[(st & RS_MASK) * 4 + col]
                                  : ring0[(st & RS_MASK) * 8 + col];
                    out[row * T + st] = x;
                }
            }
            __syncwarp();
            if (lane == 0) st_rel(&fl[2], b + 1);
        }
        return;
    }
}

extern "C" void kernel_launch(void* const* d_in, const int* in_sizes, int n_in,
                              void* d_out, int out_size) {
    const float* in_mat = (const float*)d_in[0];
    const float* w12    = (const float*)d_in[1];
    int n_mat = in_sizes[0];
    int T = out_size / 10;
    izh_net5<<<1, 128>>>(in_mat, n_mat, w12, (float*)d_out, T);
}